// round 4
// baseline (speedup 1.0000x reference)
#include <cuda_runtime.h>
#include <cuda_bf16.h>
#include <cstdint>
#include <cstddef>

// ---------------------------------------------------------------------------
// MiniBatchKMeans via warp-level mma.sync (HMMA) bf16x6 split GEMM + exact
// rescue of near-ties. Plain sm_100 target (no tcgen05).
//
// N=262144 points x D=64, K=1024 clusters.
// Output (float32): [assignments (262144)][counts (1024)][sums (1024*64)]
//
// Phase 1 (assign_kernel): argmin_k (||c_k||^2 - 2 x.c_k), cross term by
// 6-term bf16 split -> error ~1e-6 worst-case. Tracks top-2 distances; points
// with (m2-m1) < THRESH are appended to a rescue list.
// Phase 2 (rescue_kernel): exact fp32 rescore of flagged points (expected
// ~200), patching assignment/counts/sums. Robust to arbitrarily tight gaps.
// ---------------------------------------------------------------------------

#define N_POINTS   262144
#define DIMS       64
#define K_CLUSTERS 1024
#define OUT_COUNTS (N_POINTS)
#define OUT_SUMS   (N_POINTS + K_CLUSTERS)

#define TILE_M     256
#define CHUNK_N    128
#define NCHUNKS    8

#define A_IMG_BYTES  (TILE_M * 128)          // 32768
#define B_IMG_BYTES  (CHUNK_N * 128)         // 16384
#define B_CHUNK_BYTES (3 * B_IMG_BYTES)      // 49152

#define SM_A       0                          // 3 images = 98304
#define SM_B       98304                      // 2 buffers x 49152 = 98304
#define SM_CSQ     196608                     // 4096
#define SMEM_TOTAL 200704

#define RESCUE_CAP 4096
#define THRESH     2e-5f

__device__ float g_csq[K_CLUSTERS];
__device__ uint4 g_bsplit[NCHUNKS * B_CHUNK_BYTES / 16];
__device__ int   g_rescue_cnt;
__device__ int   g_rescue[RESCUE_CAP];

typedef unsigned long long u64;
typedef unsigned int u32;

// ---------------------------------------------------------------------------
__device__ __forceinline__ u32 smem_u32(const void* p) {
    u32 a;
    asm("{ .reg .u64 t; cvta.to.shared.u64 t, %1; cvt.u32.u64 %0, t; }" : "=r"(a) : "l"(p));
    return a;
}
__device__ __forceinline__ void red_add_v4(float* p, float4 v) {
    asm volatile("red.global.add.v4.f32 [%0], {%1,%2,%3,%4};"
                 :: "l"(p), "f"(v.x), "f"(v.y), "f"(v.z), "f"(v.w) : "memory");
}
__device__ __forceinline__ void cp16(u32 s, const void* g) {
    asm volatile("cp.async.cg.shared.global [%0], [%1], 16;" :: "r"(s), "l"(g) : "memory");
}
__device__ __forceinline__ void cp_commit() {
    asm volatile("cp.async.commit_group;" ::: "memory");
}
__device__ __forceinline__ void ldsm_x4(u32* r, u32 addr) {
    asm volatile("ldmatrix.sync.aligned.m8n8.x4.shared.b16 {%0,%1,%2,%3}, [%4];"
                 : "=r"(r[0]), "=r"(r[1]), "=r"(r[2]), "=r"(r[3]) : "r"(addr));
}
__device__ __forceinline__ void mma16816(float* c, const u32* a, u32 b0, u32 b1) {
    asm volatile(
        "mma.sync.aligned.m16n8k16.row.col.f32.bf16.bf16.f32 "
        "{%0,%1,%2,%3}, {%4,%5,%6,%7}, {%8,%9}, {%0,%1,%2,%3};"
        : "+f"(c[0]), "+f"(c[1]), "+f"(c[2]), "+f"(c[3])
        : "r"(a[0]), "r"(a[1]), "r"(a[2]), "r"(a[3]), "r"(b0), "r"(b1));
}

__device__ __forceinline__ void split3(float x, __nv_bfloat16& a, __nv_bfloat16& b, __nv_bfloat16& c) {
    a = __float2bfloat16(x);
    float r = x - __bfloat162float(a);
    b = __float2bfloat16(r);
    float r2 = r - __bfloat162float(b);
    c = __float2bfloat16(r2);
}
__device__ __forceinline__ __nv_bfloat162 mk2(__nv_bfloat16 a, __nv_bfloat16 b) {
    __nv_bfloat162 v; v.x = a; v.y = b; return v;
}

// ---------------------------------------------------------------------------
__global__ void zero_kernel(float* __restrict__ out) {
    int i = blockIdx.x * blockDim.x + threadIdx.x;
    const int n = K_CLUSTERS + K_CLUSTERS * DIMS;
    if (i < n) out[OUT_COUNTS + i] = 0.0f;
    if (i == 0) g_rescue_cnt = 0;
}

__global__ void csq_kernel(const float* __restrict__ cents) {
    int c = blockIdx.x * blockDim.x + threadIdx.x;
    if (c < K_CLUSTERS) {
        const float4* r = (const float4*)(cents + (size_t)c * DIMS);
        float s = 0.0f;
#pragma unroll
        for (int i = 0; i < 16; i++) {
            float4 v = r[i];
            s = fmaf(v.x, v.x, fmaf(v.y, v.y, fmaf(v.z, v.z, fmaf(v.w, v.w, s))));
        }
        g_csq[c] = s;
    }
}

__global__ void bsplit_kernel(const float* __restrict__ cents) {
    const int ch = blockIdx.x;
    const int r  = threadIdx.x;
    char* img = (char*)g_bsplit + (size_t)ch * B_CHUNK_BYTES;
    const float4* src = (const float4*)(cents + (size_t)(ch * CHUNK_N + r) * DIMS);
    const u32 ro = (u32)r * 128;
    const u32 sw = ((u32)(r & 7)) << 4;
#pragma unroll
    for (int v = 0; v < 16; v++) {
        float4 q = src[v];
        float f[4] = {q.x, q.y, q.z, q.w};
        __nv_bfloat16 s1[4], s2[4], s3[4];
#pragma unroll
        for (int p = 0; p < 4; p++) split3(f[p], s1[p], s2[p], s3[p]);
        const u32 o0 = ro + (((u32)(v * 8)) ^ sw);
        const u32 o1 = ro + (((u32)(v * 8 + 4)) ^ sw);
        *(__nv_bfloat162*)(img + o0) = mk2(s1[0], s1[1]);
        *(__nv_bfloat162*)(img + o1) = mk2(s1[2], s1[3]);
        *(__nv_bfloat162*)(img + B_IMG_BYTES + o0) = mk2(s2[0], s2[1]);
        *(__nv_bfloat162*)(img + B_IMG_BYTES + o1) = mk2(s2[2], s2[3]);
        *(__nv_bfloat162*)(img + 2 * B_IMG_BYTES + o0) = mk2(s3[0], s3[1]);
        *(__nv_bfloat162*)(img + 2 * B_IMG_BYTES + o1) = mk2(s3[2], s3[3]);
    }
}

// ---------------------------------------------------------------------------
extern __shared__ char smem[];

__global__ __launch_bounds__(256, 1)
void assign_kernel(const float* __restrict__ batch, float* __restrict__ out) {
    const u32 sb  = smem_u32(smem);
    const int tid  = threadIdx.x;
    const int lane = tid & 31;
    const int wid  = tid >> 5;
    const int wm   = wid >> 1;
    const int wn   = wid & 1;
    const int gid  = lane >> 2;
    const int tig  = lane & 3;
    const int m0   = blockIdx.x * TILE_M;

    // kick off B chunk 0
    {
        const char* g = (const char*)g_bsplit;
        const u32 s = sb + SM_B;
#pragma unroll
        for (int i = 0; i < 12; i++) {
            const u32 off = (u32)(tid + i * 256) * 16;
            cp16(s + off, g + off);
        }
        cp_commit();
    }

    {
        float* s_csq = (float*)(smem + SM_CSQ);
#pragma unroll
        for (int i = 0; i < 4; i++) s_csq[tid + 256 * i] = g_csq[tid + 256 * i];
    }

    // A tile -> 3 swizzled bf16 images
    {
        const float4* src = (const float4*)(batch + (size_t)(m0 + tid) * DIMS);
        char* A = smem + SM_A;
        const u32 ro = (u32)tid * 128;
        const u32 sw = ((u32)(tid & 7)) << 4;
#pragma unroll
        for (int v = 0; v < 16; v++) {
            float4 q = src[v];
            float f[4] = {q.x, q.y, q.z, q.w};
            __nv_bfloat16 s1[4], s2[4], s3[4];
#pragma unroll
            for (int p = 0; p < 4; p++) split3(f[p], s1[p], s2[p], s3[p]);
            const u32 o0 = ro + (((u32)(v * 8)) ^ sw);
            const u32 o1 = ro + (((u32)(v * 8 + 4)) ^ sw);
            *(__nv_bfloat162*)(A + o0) = mk2(s1[0], s1[1]);
            *(__nv_bfloat162*)(A + o1) = mk2(s1[2], s1[3]);
            *(__nv_bfloat162*)(A + A_IMG_BYTES + o0) = mk2(s2[0], s2[1]);
            *(__nv_bfloat162*)(A + A_IMG_BYTES + o1) = mk2(s2[2], s2[3]);
            *(__nv_bfloat162*)(A + 2 * A_IMG_BYTES + o0) = mk2(s3[0], s3[1]);
            *(__nv_bfloat162*)(A + 2 * A_IMG_BYTES + o1) = mk2(s3[2], s3[3]);
        }
    }
    __syncthreads();

    const u32 swzm = ((u32)(lane & 7)) << 4;
    const u32 abase = sb + SM_A + (u32)(wm * 64 + (lane & 15)) * 128;
    const u32 axk   = ((u32)(lane >> 4) * 16) ^ swzm;
    const u32 brow  = sb + SM_B + (u32)(wn * 64 + ((lane >> 4) & 1) * 8 + (lane & 7)) * 128;
    const u32 bxk   = ((u32)((lane >> 3) & 1) * 16) ^ swzm;

    float minv[8], min2[8];
    int   mini[8];
#pragma unroll
    for (int s = 0; s < 8; s++) { minv[s] = 3.4028235e38f; min2[s] = 3.4028235e38f; mini[s] = 0; }

    const float* s_csq = (const float*)(smem + SM_CSQ);

    for (int c = 0; c < NCHUNKS; c++) {
        if (c < NCHUNKS - 1) {
            const char* g = (const char*)g_bsplit + (size_t)(c + 1) * B_CHUNK_BYTES;
            const u32 s = sb + SM_B + (u32)((c + 1) & 1) * B_CHUNK_BYTES;
#pragma unroll
            for (int i = 0; i < 12; i++) {
                const u32 off = (u32)(tid + i * 256) * 16;
                cp16(s + off, g + off);
            }
            cp_commit();
            asm volatile("cp.async.wait_group 1;" ::: "memory");
        } else {
            asm volatile("cp.async.wait_group 0;" ::: "memory");
        }
        __syncthreads();

        const u32 bbase = brow + (u32)(c & 1) * B_CHUNK_BYTES;

        float acc[4][8][4];
#pragma unroll
        for (int mt = 0; mt < 4; mt++)
#pragma unroll
            for (int nt = 0; nt < 8; nt++)
#pragma unroll
                for (int k = 0; k < 4; k++) acc[mt][nt][k] = 0.0f;

#pragma unroll
        for (int ai = 0; ai < 3; ai++) {
#pragma unroll
            for (int ks = 0; ks < 4; ks++) {
                u32 a[4][4];
                const u32 kxa = ((u32)(ks * 32)) ^ axk;
#pragma unroll
                for (int mt = 0; mt < 4; mt++)
                    ldsm_x4(a[mt], abase + (u32)ai * A_IMG_BYTES + (u32)mt * 2048 + kxa);
                const int nbj = 3 - ai;
#pragma unroll
                for (int bj = 0; bj < nbj; bj++) {
                    u32 b[4][4];
                    const u32 kxb = ((u32)(ks * 32)) ^ bxk;
#pragma unroll
                    for (int nb = 0; nb < 4; nb++)
                        ldsm_x4(b[nb], bbase + (u32)bj * B_IMG_BYTES + (u32)nb * 2048 + kxb);
#pragma unroll
                    for (int mt = 0; mt < 4; mt++)
#pragma unroll
                        for (int nb = 0; nb < 4; nb++) {
                            mma16816(acc[mt][2 * nb],     a[mt], b[nb][0], b[nb][1]);
                            mma16816(acc[mt][2 * nb + 1], a[mt], b[nb][2], b[nb][3]);
                        }
                }
            }
        }

        // epilogue with top-2 tracking
        const int nb0 = c * CHUNK_N + wn * 64 + tig * 2;
#pragma unroll
        for (int nt = 0; nt < 8; nt++) {
            const float cs0 = s_csq[nb0 + nt * 8];
            const float cs1 = s_csq[nb0 + nt * 8 + 1];
#pragma unroll
            for (int mt = 0; mt < 4; mt++) {
#pragma unroll
                for (int h = 0; h < 2; h++) {
                    const int q = mt * 2 + h;
                    float d;
                    d = fmaf(-2.0f, acc[mt][nt][2 * h], cs0);
                    if (d < minv[q]) { min2[q] = minv[q]; minv[q] = d; mini[q] = nb0 + nt * 8; }
                    else if (d < min2[q]) min2[q] = d;
                    d = fmaf(-2.0f, acc[mt][nt][2 * h + 1], cs1);
                    if (d < minv[q]) { min2[q] = minv[q]; minv[q] = d; mini[q] = nb0 + nt * 8 + 1; }
                    else if (d < min2[q]) min2[q] = d;
                }
            }
        }
        __syncthreads();
    }

    float* redv  = (float*)(smem + SM_B);
    int*   redi  = (int*)(smem + SM_B + 2048);
    float* redv2 = (float*)(smem + SM_B + 4096);
    int*   s_assign = (int*)(smem + SM_CSQ);

#pragma unroll
    for (int s = 0; s < 8; s++) {
        float v1 = minv[s], v2 = min2[s];
        int   vi = mini[s];
#pragma unroll
        for (int msk = 1; msk <= 2; msk <<= 1) {
            const float o1 = __shfl_xor_sync(0xffffffffu, v1, msk);
            const float o2 = __shfl_xor_sync(0xffffffffu, v2, msk);
            const int   oi = __shfl_xor_sync(0xffffffffu, vi, msk);
            if (o1 < v1 || (o1 == v1 && oi < vi)) {
                const float nm2 = fminf(v1, fminf(v2, o2));
                v1 = o1; vi = oi; v2 = nm2;
            } else {
                v2 = fminf(o1, fminf(v2, o2));
            }
        }
        if (tig == 0) {
            const int mt = s >> 1, half = s & 1;
            const int row = wm * 64 + mt * 16 + half * 8 + gid;
            redv[row * 2 + wn]  = v1;
            redi[row * 2 + wn]  = vi;
            redv2[row * 2 + wn] = v2;
        }
    }
    __syncthreads();

    // combine the two N-warps; write assignment; flag near-ties
    {
        const float a1 = redv[tid * 2],     b1 = redv[tid * 2 + 1];
        const float a2 = redv2[tid * 2],    b2 = redv2[tid * 2 + 1];
        const int   ai = redi[tid * 2],     bi = redi[tid * 2 + 1];
        int best; float m1c, m2c;
        if (b1 < a1 || (b1 == a1 && bi < ai)) {
            best = bi; m1c = b1; m2c = fminf(a1, fminf(a2, b2));
        } else {
            best = ai; m1c = a1; m2c = fminf(b1, fminf(a2, b2));
        }
        s_assign[tid] = best;
        out[m0 + tid] = (float)best;
        if (m2c - m1c < THRESH) {
            const int slot = atomicAdd(&g_rescue_cnt, 1);
            if (slot < RESCUE_CAP) g_rescue[slot] = m0 + tid;
        }
    }
    __syncthreads();

    // fused scatter: counts + sums
    {
        const int a = s_assign[tid];
        const float4* src = (const float4*)(batch + (size_t)(m0 + tid) * DIMS);
        float* dst = out + OUT_SUMS + (size_t)a * DIMS;
#pragma unroll
        for (int i = 0; i < 16; i++) red_add_v4(dst + i * 4, src[i]);
        atomicAdd(out + OUT_COUNTS + a, 1.0f);
    }
}

// ---------------------------------------------------------------------------
// Exact fp32 rescore for flagged points; patches assignment/counts/sums.
__global__ void rescue_kernel(const float* __restrict__ batch,
                              const float* __restrict__ cents,
                              float* __restrict__ out) {
    __shared__ float xs[64];
    __shared__ float sv[128];
    __shared__ int   si[128];
    __shared__ int   s_old, s_new;

    const int b = blockIdx.x;
    if (b >= g_rescue_cnt || b >= RESCUE_CAP) return;
    const int p = g_rescue[b];
    const int tid = threadIdx.x;

    if (tid < 16) ((float4*)xs)[tid] = ((const float4*)(batch + (size_t)p * DIMS))[tid];
    __syncthreads();

    float bm = 3.4028235e38f;
    int   bi = 0;
    for (int i = 0; i < 8; i++) {
        const int c = tid + i * 128;
        const float* cr = cents + (size_t)c * DIMS;
        float dot = 0.0f;
#pragma unroll
        for (int d = 0; d < DIMS; d++) dot = fmaf(xs[d], cr[d], dot);
        const float dist = fmaf(-2.0f, dot, g_csq[c]);
        if (dist < bm) { bm = dist; bi = c; }   // c ascending: strict keeps lowest idx
    }
    sv[tid] = bm; si[tid] = bi;
    __syncthreads();
    for (int s = 64; s > 0; s >>= 1) {
        if (tid < s) {
            const float ov = sv[tid + s];
            const int   oi = si[tid + s];
            if (ov < sv[tid] || (ov == sv[tid] && oi < si[tid])) { sv[tid] = ov; si[tid] = oi; }
        }
        __syncthreads();
    }
    if (tid == 0) {
        s_new = si[0];
        s_old = (int)out[p];
        if (s_new != s_old) {
            out[p] = (float)s_new;
            atomicAdd(out + OUT_COUNTS + s_old, -1.0f);
            atomicAdd(out + OUT_COUNTS + s_new,  1.0f);
        }
    }
    __syncthreads();
    const int oldc = s_old, newc = s_new;
    if (newc != oldc && tid < 32) {
        const int r = tid & 15;
        float4 v = ((const float4*)(batch + (size_t)p * DIMS))[r];
        if (tid < 16) {
            const float4 nv = make_float4(-v.x, -v.y, -v.z, -v.w);
            red_add_v4(out + OUT_SUMS + (size_t)oldc * DIMS + r * 4, nv);
        } else {
            red_add_v4(out + OUT_SUMS + (size_t)newc * DIMS + r * 4, v);
        }
    }
}

// ---------------------------------------------------------------------------
extern "C" void kernel_launch(void* const* d_in, const int* in_sizes, int n_in,
                              void* d_out, int out_size) {
    const float* batch = (const float*)d_in[0];
    const float* cents = (const float*)d_in[1];
    float* out = (float*)d_out;

    cudaFuncSetAttribute(assign_kernel,
                         cudaFuncAttributeMaxDynamicSharedMemorySize, SMEM_TOTAL);

    const int zero_n = K_CLUSTERS + K_CLUSTERS * DIMS;
    zero_kernel<<<(zero_n + 255) / 256, 256>>>(out);
    csq_kernel<<<(K_CLUSTERS + 255) / 256, 256>>>(cents);
    bsplit_kernel<<<NCHUNKS, CHUNK_N>>>(cents);
    assign_kernel<<<N_POINTS / TILE_M, 256, SMEM_TOTAL>>>(batch, out);
    rescue_kernel<<<RESCUE_CAP, 128>>>(batch, cents, out);
}